// round 1
// baseline (speedup 1.0000x reference)
#include <cuda_runtime.h>

#define NN 50000
#define NE 400000
#define DD 512
#define KK2 1024   /* 2*D: [agg | z] concat */
#define LL 3

// ---------------- scratch (device globals; no allocs allowed) ----------------
__device__ float g_agg[(size_t)NN * DD];     // 102.4 MB
__device__ float g_zbuf1[(size_t)NN * DD];   // 102.4 MB
__device__ float g_zbuf2[(size_t)NN * DD];   // 102.4 MB
__device__ float g_invdeg[NN];
__device__ int   g_src[NE];
__device__ int   g_dst[NN > NE ? NN : NE];   // NE
__device__ int   g_is32;

// ---------------- small init / index normalization ----------------
__global__ void zero_small_kernel() {
    int i = blockIdx.x * blockDim.x + threadIdx.x;
    if (i < NN) g_invdeg[i] = 0.0f;
    if (i == 0) g_is32 = 0;
}

// If edge_index is int64, every odd 32-bit word (high half) is 0 (indices < 50000).
// If it's int32, odd words are real indices -> almost surely nonzero among 4096.
__global__ void detect_kernel(const unsigned int* __restrict__ raw) {
    unsigned acc = 0;
    for (int j = threadIdx.x; j < 4096; j += blockDim.x) acc |= raw[2 * j + 1];
    if (acc) atomicOr(&g_is32, 1);
}

__global__ void convert_kernel(const void* __restrict__ raw) {
    int e = blockIdx.x * blockDim.x + threadIdx.x;
    if (e >= NE) return;
    int s, d;
    if (g_is32) {
        const int* p = (const int*)raw;
        s = p[e];
        d = p[NE + e];
    } else {
        const long long* p = (const long long*)raw;
        s = (int)p[e];
        d = (int)p[NE + e];
    }
    g_src[e] = s;
    g_dst[e] = d;
}

__global__ void deg_kernel() {
    int e = blockIdx.x * blockDim.x + threadIdx.x;
    if (e >= NE) return;
    atomicAdd(&g_invdeg[g_dst[e]], 1.0f);
}

__global__ void invdeg_kernel() {
    int i = blockIdx.x * blockDim.x + threadIdx.x;
    if (i >= NN) return;
    float d = g_invdeg[i];
    g_invdeg[i] = (d > 0.0f) ? 1.0f / d : 0.0f;
}

__global__ void zero_agg_kernel() {
    size_t i = ((size_t)blockIdx.x * blockDim.x + threadIdx.x) * 4;
    if (i < (size_t)NN * DD)
        *(float4*)&g_agg[i] = make_float4(0.f, 0.f, 0.f, 0.f);
}

// ---------------- edge scatter: agg[dst] += w * z[src] ----------------
// One block per edge, 128 threads x float4 = 512 floats.
__global__ void __launch_bounds__(128) scatter_kernel(
    const float* __restrict__ xext, int insel, const float* __restrict__ ew) {
    const float* zin = (insel == 0) ? xext : (insel == 1 ? g_zbuf1 : g_zbuf2);
    int e = blockIdx.x;
    int s = g_src[e];
    int d = g_dst[e];
    float w = __ldg(&ew[e]);
    float4 v = *((const float4*)(zin + (size_t)s * DD) + threadIdx.x);
    v.x *= w; v.y *= w; v.z *= w; v.w *= w;
    float* ap = g_agg + (size_t)d * DD + (size_t)threadIdx.x * 4;
    asm volatile("red.global.add.v4.f32 [%0], {%1,%2,%3,%4};"
                 :: "l"(ap), "f"(v.x), "f"(v.y), "f"(v.z), "f"(v.w)
                 : "memory");
}

// ---------------- fused SGEMM: z' = relu([agg*invdeg | z] @ [Wl;Wr] + b) ----
// C[50000,512] = A[50000,1024] * B[1024,512]; 128x128x8 tile, 8x8 microtile.
__global__ void __launch_bounds__(256) gemm_kernel(
    const float* __restrict__ xext, int insel,
    const float* __restrict__ Wl, const float* __restrict__ Wr,
    const float* __restrict__ bias,
    float* __restrict__ outext, int outsel) {
    const float* zin = (insel == 0) ? xext : (insel == 1 ? g_zbuf1 : g_zbuf2);
    float* zout = (outsel == 0) ? g_zbuf1 : (outsel == 1 ? g_zbuf2 : outext);

    __shared__ float As[8][128];
    __shared__ float Bs[8][128];

    int tid = threadIdx.x;
    int m0 = blockIdx.y * 128;
    int n0 = blockIdx.x * 128;
    int tm = tid >> 4;       // 0..15
    int tn = tid & 15;       // 0..15

    float acc[8][8];
#pragma unroll
    for (int i = 0; i < 8; i++)
#pragma unroll
        for (int j = 0; j < 8; j++) acc[i][j] = 0.0f;

    // A-load mapping: 128 rows x 8 k, thread -> (row = tid/2, k4 = (tid&1)*4)
    int ar = tid >> 1;
    int ak = (tid & 1) << 2;
    int arow = m0 + ar;
    bool arow_ok = arow < NN;
    float idg = arow_ok ? g_invdeg[arow] : 0.0f;
    const float* aggrow = g_agg + (size_t)arow * DD;
    const float* zrow = zin + (size_t)arow * DD;

    // B-load mapping: 8 k x 128 n, thread -> (k = tid/32, n4 = (tid&31)*4)
    int brk = tid >> 5;
    int bn = (tid & 31) << 2;

    for (int kt = 0; kt < KK2; kt += 8) {
        // load A tile (virtual concat [agg*invdeg | z])
        int k = kt + ak;
        float4 av = make_float4(0.f, 0.f, 0.f, 0.f);
        if (arow_ok) {
            if (k < DD) {
                av = *(const float4*)(aggrow + k);
                av.x *= idg; av.y *= idg; av.z *= idg; av.w *= idg;
            } else {
                av = *(const float4*)(zrow + (k - DD));
            }
        }
        As[ak + 0][ar] = av.x;
        As[ak + 1][ar] = av.y;
        As[ak + 2][ar] = av.z;
        As[ak + 3][ar] = av.w;

        // load B tile (virtual stack [Wl; Wr])
        int bk = kt + brk;
        const float* bp = (bk < DD) ? (Wl + (size_t)bk * DD + n0 + bn)
                                    : (Wr + (size_t)(bk - DD) * DD + n0 + bn);
        *(float4*)&Bs[brk][bn] = *(const float4*)bp;

        __syncthreads();

#pragma unroll
        for (int kk = 0; kk < 8; kk++) {
            float a[8], bb[8];
            *(float4*)(a + 0) = *(float4*)&As[kk][tm * 8 + 0];
            *(float4*)(a + 4) = *(float4*)&As[kk][tm * 8 + 4];
            *(float4*)(bb + 0) = *(float4*)&Bs[kk][tn * 8 + 0];
            *(float4*)(bb + 4) = *(float4*)&Bs[kk][tn * 8 + 4];
#pragma unroll
            for (int i = 0; i < 8; i++)
#pragma unroll
                for (int j = 0; j < 8; j++)
                    acc[i][j] += a[i] * bb[j];
        }
        __syncthreads();
    }

    // epilogue: bias + relu
#pragma unroll
    for (int i = 0; i < 8; i++) {
        int r = m0 + tm * 8 + i;
        if (r < NN) {
#pragma unroll
            for (int j = 0; j < 8; j += 4) {
                int c = n0 + tn * 8 + j;
                float4 v;
                v.x = fmaxf(acc[i][j + 0] + bias[c + 0], 0.0f);
                v.y = fmaxf(acc[i][j + 1] + bias[c + 1], 0.0f);
                v.z = fmaxf(acc[i][j + 2] + bias[c + 2], 0.0f);
                v.w = fmaxf(acc[i][j + 3] + bias[c + 3], 0.0f);
                *(float4*)(zout + (size_t)r * DD + c) = v;
            }
        }
    }
}

// ---------------- launch ----------------
extern "C" void kernel_launch(void* const* d_in, const int* in_sizes, int n_in,
                              void* d_out, int out_size) {
    (void)in_sizes; (void)n_in; (void)out_size;
    const float* x  = (const float*)d_in[0];
    const void*  ei = d_in[1];
    const float* ew = (const float*)d_in[2];
    const float* Wl = (const float*)d_in[3];
    const float* Wr = (const float*)d_in[4];
    const float* b  = (const float*)d_in[5];
    float* out = (float*)d_out;

    zero_small_kernel<<<(NN + 255) / 256, 256>>>();
    detect_kernel<<<1, 256>>>((const unsigned int*)ei);
    convert_kernel<<<(NE + 255) / 256, 256>>>(ei);
    deg_kernel<<<(NE + 255) / 256, 256>>>();
    invdeg_kernel<<<(NN + 255) / 256, 256>>>();

    const int nzero = (int)(((size_t)NN * DD / 4 + 255) / 256);
    dim3 ggrid(4, (NN + 127) / 128);  // N-tiles x M-tiles

    // layer 0: x -> zbuf1 ; layer 1: zbuf1 -> zbuf2 ; layer 2: zbuf2 -> out
    for (int l = 0; l < LL; l++) {
        int insel  = (l == 0) ? 0 : l;          // 0:x 1:zbuf1 2:zbuf2
        int outsel = (l == LL - 1) ? 2 : l;     // 0:zbuf1 1:zbuf2 2:external
        zero_agg_kernel<<<nzero, 256>>>();
        scatter_kernel<<<NE, 128>>>(x, insel, ew);
        gemm_kernel<<<ggrid, 256>>>(x, insel,
                                    Wl + (size_t)l * DD * DD,
                                    Wr + (size_t)l * DD * DD,
                                    b + (size_t)l * DD,
                                    out, outsel);
    }
}

// round 6
// speedup vs baseline: 1.6574x; 1.6574x over previous
#include <cuda_runtime.h>
#include <cuda_bf16.h>
#include <cstdint>

#define NN 50000
#define NE 400000
#define DD 512
#define LL 3
#define BM 128
#define BN 256
#define NCHK 32            /* k chunks of 32 over K=1024 ([agg | z]) */

/* smem u32 word offsets: pair-packed tiles, padded strides (136/264) */
#define AHI_W 0
#define ALO_W 2176          /* 16*136 */
#define BHI_W 4352
#define BLO_W 8576          /* 4352 + 16*264 */
#define SMEM_WORDS 12800
#define SMEM_BYTES (SMEM_WORDS * 4)

// ---------------- device scratch (no allocs allowed) ----------------
__device__ float g_agg[(size_t)NN * DD];
__device__ float g_z1[(size_t)NN * DD];
__device__ float g_z2[(size_t)NN * DD];
__device__ float g_invdeg[NN];
__device__ int   g_src[NE];
__device__ int   g_dst[NE];
__device__ int   g_is32;

// ---------------- helpers ----------------
__device__ __forceinline__ unsigned short bf16_bits(__nv_bfloat16 h) {
    return reinterpret_cast<unsigned short&>(h);
}
// pack hi-split of (v0,v1) into hw, lo-split into lw (v0 in low 16 bits)
__device__ __forceinline__ void split_pack(float v0, float v1, unsigned& hw, unsigned& lw) {
    __nv_bfloat16 h0 = __float2bfloat16(v0), h1 = __float2bfloat16(v1);
    __nv_bfloat16 l0 = __float2bfloat16(v0 - __bfloat162float(h0));
    __nv_bfloat16 l1 = __float2bfloat16(v1 - __bfloat162float(h1));
    hw = (unsigned)bf16_bits(h0) | ((unsigned)bf16_bits(h1) << 16);
    lw = (unsigned)bf16_bits(l0) | ((unsigned)bf16_bits(l1) << 16);
}

#define MMA16816(d, a, b0, b1)                                                    \
    asm volatile("mma.sync.aligned.m16n8k16.row.col.f32.bf16.bf16.f32 "           \
                 "{%0,%1,%2,%3}, {%4,%5,%6,%7}, {%8,%9}, {%0,%1,%2,%3};"          \
                 : "+f"((d)[0]), "+f"((d)[1]), "+f"((d)[2]), "+f"((d)[3])         \
                 : "r"((a)[0]), "r"((a)[1]), "r"((a)[2]), "r"((a)[3]),            \
                   "r"(b0), "r"(b1))

// ---------------- small prep kernels (validated in R1) ----------------
__global__ void zero_small_kernel() {
    int i = blockIdx.x * blockDim.x + threadIdx.x;
    if (i < NN) g_invdeg[i] = 0.0f;
    if (i == 0) g_is32 = 0;
}

__global__ void detect_kernel(const unsigned int* __restrict__ raw) {
    unsigned acc = 0;
    for (int j = threadIdx.x; j < 4096; j += blockDim.x) acc |= raw[2 * j + 1];
    if (acc) atomicOr(&g_is32, 1);
}

__global__ void convert_kernel(const void* __restrict__ raw) {
    int e = blockIdx.x * blockDim.x + threadIdx.x;
    if (e >= NE) return;
    int s, d;
    if (g_is32) {
        const int* p = (const int*)raw;
        s = p[e]; d = p[NE + e];
    } else {
        const long long* p = (const long long*)raw;
        s = (int)p[e]; d = (int)p[NE + e];
    }
    g_src[e] = s; g_dst[e] = d;
}

__global__ void deg_kernel() {
    int e = blockIdx.x * blockDim.x + threadIdx.x;
    if (e >= NE) return;
    atomicAdd(&g_invdeg[g_dst[e]], 1.0f);
}

__global__ void invdeg_kernel() {
    int i = blockIdx.x * blockDim.x + threadIdx.x;
    if (i >= NN) return;
    float d = g_invdeg[i];
    g_invdeg[i] = (d > 0.0f) ? 1.0f / d : 0.0f;
}

__global__ void zero_agg_kernel() {
    size_t i = ((size_t)blockIdx.x * blockDim.x + threadIdx.x) * 4;
    if (i < (size_t)NN * DD)
        *(float4*)&g_agg[i] = make_float4(0.f, 0.f, 0.f, 0.f);
}

// ---------------- edge scatter: agg[dst] += w * z[src] (R1-validated) ----
__global__ void __launch_bounds__(128) scatter_kernel(
    const float* __restrict__ xext, int insel, const float* __restrict__ ew) {
    const float* zin = (insel == 0) ? xext : (insel == 1 ? g_z1 : g_z2);
    int e = blockIdx.x;
    int s = g_src[e];
    int d = g_dst[e];
    float w = __ldg(&ew[e]);
    float4 v = *((const float4*)(zin + (size_t)s * DD) + threadIdx.x);
    v.x *= w; v.y *= w; v.z *= w; v.w *= w;
    float* ap = g_agg + (size_t)d * DD + (size_t)threadIdx.x * 4;
    asm volatile("red.global.add.v4.f32 [%0], {%1,%2,%3,%4};"
                 :: "l"(ap), "f"(v.x), "f"(v.y), "f"(v.z), "f"(v.w) : "memory");
}

// ---------------- GEMM: inline bf16 hi/lo split, fp32 inputs ----------------
// out[m, n] = relu( bias[n] + sum_k [agg*invdeg | z][m][k] * [Wl; Wr][k][n] )
// C tile 128x256, 8 warps (2x4 of 64x64). Each 32-k chunk: load fp32,
// split to bf16 pairs in smem, 3 mma products (AhiBhi + AhiBlo + AloBhi).
__global__ void __launch_bounds__(256, 1) gemm_kernel(
    const float* __restrict__ xext, int insel,
    const float* __restrict__ Wl, const float* __restrict__ Wr,
    const float* __restrict__ bias,
    float* __restrict__ outext, int outsel) {
    const float* zsrc = (insel == 0) ? xext : (insel == 1 ? g_z1 : g_z2);
    float* zout = (outsel == 0) ? g_z1 : (outsel == 1 ? g_z2 : outext);

    extern __shared__ uint32_t sw[];
    int tid = threadIdx.x, lane = tid & 31, warp = tid >> 5;
    int wm = warp >> 2, wn = warp & 3;
    int m0 = blockIdx.y * BM, n0 = blockIdx.x * BN;
    int g = lane >> 2, c = lane & 3;

    float acc[4][8][4];
#pragma unroll
    for (int i = 0; i < 4; i++)
#pragma unroll
        for (int j = 0; j < 8; j++)
#pragma unroll
            for (int q = 0; q < 4; q++) acc[i][j][q] = 0.0f;

    // A loader mapping: thread -> (row m = tid>>1, k-half = (tid&1)*16)
    int am = m0 + (tid >> 1);
    int amc = (am < NN) ? am : (NN - 1);       // clamp; contributions masked in epilogue
    int ako = (tid & 1) * 16;
    int acol = tid >> 1;
    float idg_m = g_invdeg[amc];
    const float* aggrow = g_agg + (size_t)amc * DD;
    const float* zrow = zsrc + (size_t)amc * DD;
    // B loader mapping: thread -> (k-pair p = tid>>4, n offset (tid&15)*16)
    int bp = tid >> 4;
    int bnb = (tid & 15) * 16;

    for (int kc = 0; kc < NCHK; kc++) {
        __syncthreads();   // previous chunk's compute done before overwrite
        // ---- A: 128 rows x 32 k fp32 -> bf16 hi/lo pairs
        {
            bool isAgg = (kc < 16);
            float idg = isAgg ? idg_m : 1.0f;
            const float* ap = (isAgg ? (aggrow + kc * 32)
                                     : (zrow + (kc - 16) * 32)) + ako;
            float4 q0 = ((const float4*)ap)[0];
            float4 q1 = ((const float4*)ap)[1];
            float4 q2 = ((const float4*)ap)[2];
            float4 q3 = ((const float4*)ap)[3];
            float f[16] = {q0.x, q0.y, q0.z, q0.w, q1.x, q1.y, q1.z, q1.w,
                           q2.x, q2.y, q2.z, q2.w, q3.x, q3.y, q3.z, q3.w};
            int pbase = (tid & 1) * 8;
#pragma unroll
            for (int e = 0; e < 8; e++) {
                unsigned hw, lw;
                split_pack(f[2 * e] * idg, f[2 * e + 1] * idg, hw, lw);
                sw[AHI_W + (pbase + e) * 136 + acol] = hw;
                sw[ALO_W + (pbase + e) * 136 + acol] = lw;
            }
        }
        // ---- B: 32 k x 256 n fp32 -> bf16 hi/lo pairs
        {
            int kg = kc * 32 + 2 * bp;         // even; kg,kg+1 same side of 512
            const float* w0 = ((kg < DD) ? (Wl + (size_t)kg * DD)
                                         : (Wr + (size_t)(kg - DD) * DD)) + n0 + bnb;
            const float* w1 = w0 + DD;
            float4 u0 = ((const float4*)w0)[0], u1 = ((const float4*)w0)[1],
                   u2 = ((const float4*)w0)[2], u3 = ((const float4*)w0)[3];
            float4 v0 = ((const float4*)w1)[0], v1 = ((const float4*)w1)[1],
                   v2 = ((const float4*)w1)[2], v3 = ((const float4*)w1)[3];
            float r0[16] = {u0.x, u0.y, u0.z, u0.w, u1.x, u1.y, u1.z, u1.w,
                            u2.x, u2.y, u2.z, u2.w, u3.x, u3.y, u3.z, u3.w};
            float r1[16] = {v0.x, v0.y, v0.z, v0.w, v1.x, v1.y, v1.z, v1.w,
                            v2.x, v2.y, v2.z, v2.w, v3.x, v3.y, v3.z, v3.w};
            unsigned hib[16], lob[16];
#pragma unroll
            for (int e = 0; e < 16; e++)
                split_pack(r0[e], r1[e], hib[e], lob[e]);  // pair (k=2p, k=2p+1)
            int wbase = bp * 264 + bnb;
#pragma unroll
            for (int q = 0; q < 4; q++) {
                *(uint4*)&sw[BHI_W + wbase + 4 * q] =
                    make_uint4(hib[4 * q], hib[4 * q + 1], hib[4 * q + 2], hib[4 * q + 3]);
                *(uint4*)&sw[BLO_W + wbase + 4 * q] =
                    make_uint4(lob[4 * q], lob[4 * q + 1], lob[4 * q + 2], lob[4 * q + 3]);
            }
        }
        __syncthreads();
        // ---- compute: 2 x k16, 3 products each
#pragma unroll
        for (int ks = 0; ks < 2; ks++) {
            int ab = (8 * ks + c) * 136 + wm * 64 + g;
            int bb = (8 * ks + c) * 264 + wn * 64 + g;
            uint32_t af[4][4], bf2[4][4];
            // P1: Ahi x Bhi
#pragma unroll
            for (int i = 0; i < 4; i++) {
                int x = AHI_W + ab + i * 16;
                af[i][0] = sw[x]; af[i][1] = sw[x + 8];
                af[i][2] = sw[x + 544]; af[i][3] = sw[x + 552];
            }
#pragma unroll
            for (int j = 0; j < 4; j++) {
                int x = BHI_W + bb + j * 16;
                bf2[j][0] = sw[x]; bf2[j][1] = sw[x + 1056];
                bf2[j][2] = sw[x + 8]; bf2[j][3] = sw[x + 1064];
            }
#pragma unroll
            for (int i = 0; i < 4; i++)
#pragma unroll
                for (int j = 0; j < 4; j++) {
                    MMA16816(acc[i][2 * j], af[i], bf2[j][0], bf2[j][1]);
                    MMA16816(acc[i][2 * j + 1], af[i], bf2[j][2], bf2[j][3]);
                }
            // P2: Ahi x Blo  (af unchanged)
#pragma unroll
            for (int j = 0; j < 4; j++) {
                int x = BLO_W + bb + j * 16;
                bf2[j][0] = sw[x]; bf2[j][1] = sw[x + 1056];
                bf2[j][2] = sw[x + 8]; bf2[j][3] = sw[x + 1064];
            }
#pragma unroll
            for (int i = 0; i < 4; i++)
#pragma unroll
                for (int j = 0; j < 4; j++) {
                    MMA16816(acc[i][2 * j], af[i], bf2[j][0], bf2[j][1]);
                    MMA16816(acc[i][2 * j + 1], af[i], bf2[j][2], bf2[j][3]);
                }
            // P3: Alo x Bhi
#pragma unroll
            for (int i = 0; i < 4; i++) {
                int x = ALO_W + ab + i * 16;
                af[i][0] = sw[x]; af[i][1] = sw[x + 8];
                af[i][2] = sw[x + 544]; af[i][3] = sw[x + 552];
            }
#pragma unroll
            for (int j = 0; j < 4; j++) {
                int x = BHI_W + bb + j * 16;
                bf2[j][0] = sw[x]; bf2[j][1] = sw[x + 1056];
                bf2[j][2] = sw[x + 8]; bf2[j][3] = sw[x + 1064];
            }
#pragma unroll
            for (int i = 0; i < 4; i++)
#pragma unroll
                for (int j = 0; j < 4; j++) {
                    MMA16816(acc[i][2 * j], af[i], bf2[j][0], bf2[j][1]);
                    MMA16816(acc[i][2 * j + 1], af[i], bf2[j][2], bf2[j][3]);
                }
        }
    }

    // ---- epilogue: bias + relu, fp32 store only
    int cr = g;                 // accumulator row group
    int cc = c << 1;            // accumulator col pair
    float bj0[8], bj1[8];
#pragma unroll
    for (int j = 0; j < 8; j++) {
        int col = n0 + wn * 64 + j * 8 + cc;
        bj0[j] = __ldg(bias + col);
        bj1[j] = __ldg(bias + col + 1);
    }
#pragma unroll
    for (int i = 0; i < 4; i++) {
        int r0 = m0 + wm * 64 + i * 16 + cr;
#pragma unroll
        for (int j = 0; j < 8; j++) {
            int col = n0 + wn * 64 + j * 8 + cc;
            float v00 = fmaxf(acc[i][j][0] + bj0[j], 0.0f);
            float v01 = fmaxf(acc[i][j][1] + bj1[j], 0.0f);
            float v10 = fmaxf(acc[i][j][2] + bj0[j], 0.0f);
            float v11 = fmaxf(acc[i][j][3] + bj1[j], 0.0f);
            if (r0 < NN)
                *(float2*)(zout + (size_t)r0 * DD + col) = make_float2(v00, v01);
            if (r0 + 8 < NN)
                *(float2*)(zout + (size_t)(r0 + 8) * DD + col) = make_float2(v10, v11);
        }
    }
}

// ---------------- launch ----------------
extern "C" void kernel_launch(void* const* d_in, const int* in_sizes, int n_in,
                              void* d_out, int out_size) {
    (void)in_sizes; (void)n_in; (void)out_size;
    const float* x  = (const float*)d_in[0];
    const void*  ei = d_in[1];
    const float* ew = (const float*)d_in[2];
    const float* Wl = (const float*)d_in[3];
    const float* Wr = (const float*)d_in[4];
    const float* b  = (const float*)d_in[5];
    float* out = (float*)d_out;

    cudaFuncSetAttribute(gemm_kernel, cudaFuncAttributeMaxDynamicSharedMemorySize, SMEM_BYTES);

    zero_small_kernel<<<(NN + 255) / 256, 256>>>();
    detect_kernel<<<1, 256>>>((const unsigned int*)ei);
    convert_kernel<<<(NE + 255) / 256, 256>>>(ei);
    deg_kernel<<<(NE + 255) / 256, 256>>>();
    invdeg_kernel<<<(NN + 255) / 256, 256>>>();

    const int nzero = (int)(((size_t)NN * DD / 4 + 255) / 256);
    dim3 ggrid(2, (NN + BM - 1) / BM);   // n-blocks x m-tiles

    // layer 0: x -> g_z1 ; layer 1: g_z1 -> g_z2 ; layer 2: g_z2 -> out
    for (int l = 0; l < LL; l++) {
        int insel  = (l == 0) ? 0 : l;        // 0:x 1:g_z1 2:g_z2
        int outsel = (l == LL - 1) ? 2 : l;   // 0:g_z1 1:g_z2 2:external
        zero_agg_kernel<<<nzero, 256>>>();
        scatter_kernel<<<NE, 128>>>(x, insel, ew);
        gemm_kernel<<<ggrid, 256, SMEM_BYTES>>>(x, insel,
                                                Wl + (size_t)l * DD * DD,
                                                Wr + (size_t)l * DD * DD,
                                                b + (size_t)l * DD,
                                                out, outsel);
    }
}

// round 7
// speedup vs baseline: 2.1756x; 1.3126x over previous
#include <cuda_runtime.h>
#include <cuda_bf16.h>
#include <cstdint>

#define NN 50000
#define NE 400000
#define DD 512
#define LL 3
#define BM 128
#define BN 256
#define NCHK 32            /* k chunks of 32 over K=1024 ([agg | z]) */

/* smem u32 word offsets: pair-packed tiles, padded strides (136/264) */
#define AHI_W 0
#define ALO_W 2176          /* 16*136 */
#define BHI_W 4352
#define BLO_W 8576          /* 4352 + 16*264 */
#define SMEM_WORDS 12800
#define SMEM_BYTES (SMEM_WORDS * 4)

// ---------------- device scratch (no allocs allowed) ----------------
__device__ float g_agg[(size_t)NN * DD];
__device__ float g_z1[(size_t)NN * DD];
__device__ float g_z2[(size_t)NN * DD];
__device__ int   g_degi[NN];
__device__ int   g_off[NN + 1];
__device__ int   g_cur[NN];
__device__ int   g_csr_src[NE];
__device__ float g_csr_w[NE];
__device__ int   g_src[NE];
__device__ int   g_dst[NE];
__device__ int   g_is32;

// ---------------- helpers ----------------
__device__ __forceinline__ unsigned short bf16_bits(__nv_bfloat16 h) {
    return reinterpret_cast<unsigned short&>(h);
}
__device__ __forceinline__ void split_pack(float v0, float v1, unsigned& hw, unsigned& lw) {
    __nv_bfloat16 h0 = __float2bfloat16(v0), h1 = __float2bfloat16(v1);
    __nv_bfloat16 l0 = __float2bfloat16(v0 - __bfloat162float(h0));
    __nv_bfloat16 l1 = __float2bfloat16(v1 - __bfloat162float(h1));
    hw = (unsigned)bf16_bits(h0) | ((unsigned)bf16_bits(h1) << 16);
    lw = (unsigned)bf16_bits(l0) | ((unsigned)bf16_bits(l1) << 16);
}

#define MMA16816(d, a, b0, b1)                                                    \
    asm volatile("mma.sync.aligned.m16n8k16.row.col.f32.bf16.bf16.f32 "           \
                 "{%0,%1,%2,%3}, {%4,%5,%6,%7}, {%8,%9}, {%0,%1,%2,%3};"          \
                 : "+f"((d)[0]), "+f"((d)[1]), "+f"((d)[2]), "+f"((d)[3])         \
                 : "r"((a)[0]), "r"((a)[1]), "r"((a)[2]), "r"((a)[3]),            \
                   "r"(b0), "r"(b1))

// ---------------- prep kernels ----------------
__global__ void zero_small_kernel() {
    int i = blockIdx.x * blockDim.x + threadIdx.x;
    if (i < NN) g_degi[i] = 0;
    if (i == 0) g_is32 = 0;
}

__global__ void detect_kernel(const unsigned int* __restrict__ raw) {
    unsigned acc = 0;
    for (int j = threadIdx.x; j < 4096; j += blockDim.x) acc |= raw[2 * j + 1];
    if (acc) atomicOr(&g_is32, 1);
}

__global__ void convert_kernel(const void* __restrict__ raw) {
    int e = blockIdx.x * blockDim.x + threadIdx.x;
    if (e >= NE) return;
    int s, d;
    if (g_is32) {
        const int* p = (const int*)raw;
        s = p[e]; d = p[NE + e];
    } else {
        const long long* p = (const long long*)raw;
        s = (int)p[e]; d = (int)p[NE + e];
    }
    g_src[e] = s; g_dst[e] = d;
}

__global__ void degi_kernel() {
    int e = blockIdx.x * blockDim.x + threadIdx.x;
    if (e >= NE) return;
    atomicAdd(&g_degi[g_dst[e]], 1);
}

// single-block exclusive scan over g_degi -> g_off (NN+1), also init g_cur
__global__ void scan_kernel() {
    __shared__ int tmp[1024];
    __shared__ int carry;
    if (threadIdx.x == 0) { carry = 0; g_off[0] = 0; }
    __syncthreads();
    for (int base = 0; base < NN; base += 1024) {
        int i = base + threadIdx.x;
        int v = (i < NN) ? g_degi[i] : 0;
        tmp[threadIdx.x] = v;
        __syncthreads();
#pragma unroll
        for (int s = 1; s < 1024; s <<= 1) {
            int t = (threadIdx.x >= s) ? tmp[threadIdx.x - s] : 0;
            __syncthreads();
            tmp[threadIdx.x] += t;
            __syncthreads();
        }
        if (i < NN) {
            int incl = carry + tmp[threadIdx.x];
            g_off[i + 1] = incl;
            g_cur[i] = incl - v;   // exclusive = offset start
        }
        __syncthreads();
        if (threadIdx.x == 0) carry += tmp[1023];
        __syncthreads();
    }
}

__global__ void fill_csr_kernel(const float* __restrict__ ew) {
    int e = blockIdx.x * blockDim.x + threadIdx.x;
    if (e >= NE) return;
    int d = g_dst[e];
    int pos = atomicAdd(&g_cur[d], 1);
    g_csr_src[pos] = g_src[e];
    g_csr_w[pos] = ew[e];
}

// ---------------- CSR gather: agg[d] = invdeg * sum_e w_e * z[src_e] --------
__global__ void __launch_bounds__(128) gather_kernel(
    const float* __restrict__ xext, int insel) {
    const float* zin = (insel == 0) ? xext : (insel == 1 ? g_z1 : g_z2);
    int d = blockIdx.x;
    int beg = g_off[d], end = g_off[d + 1];
    float4 acc = make_float4(0.f, 0.f, 0.f, 0.f);
    for (int i = beg; i < end; i++) {
        int s = __ldg(&g_csr_src[i]);
        float w = __ldg(&g_csr_w[i]);
        float4 v = ((const float4*)(zin + (size_t)s * DD))[threadIdx.x];
        acc.x += w * v.x; acc.y += w * v.y;
        acc.z += w * v.z; acc.w += w * v.w;
    }
    float inv = (end > beg) ? 1.0f / (float)(end - beg) : 0.0f;
    acc.x *= inv; acc.y *= inv; acc.z *= inv; acc.w *= inv;
    ((float4*)(g_agg + (size_t)d * DD))[threadIdx.x] = acc;
}

// ---------------- GEMM: inline bf16 hi/lo split, register-prefetch pipeline --
__global__ void __launch_bounds__(256, 1) gemm_kernel(
    const float* __restrict__ xext, int insel,
    const float* __restrict__ Wl, const float* __restrict__ Wr,
    const float* __restrict__ bias,
    float* __restrict__ outext, int outsel) {
    const float* zsrc = (insel == 0) ? xext : (insel == 1 ? g_z1 : g_z2);
    float* zout = (outsel == 0) ? g_z1 : (outsel == 1 ? g_z2 : outext);

    extern __shared__ uint32_t sw[];
    int tid = threadIdx.x, lane = tid & 31, warp = tid >> 5;
    int wm = warp >> 2, wn = warp & 3;
    int m0 = blockIdx.y * BM, n0 = blockIdx.x * BN;
    int g = lane >> 2, c = lane & 3;

    float acc[4][8][4];
#pragma unroll
    for (int i = 0; i < 4; i++)
#pragma unroll
        for (int j = 0; j < 8; j++)
#pragma unroll
            for (int q = 0; q < 4; q++) acc[i][j][q] = 0.0f;

    // A loader: thread -> (row m = tid>>1, k-half (tid&1)*16)
    int am = m0 + (tid >> 1);
    int amc = (am < NN) ? am : (NN - 1);
    int ako = (tid & 1) * 16;
    int acol = tid >> 1;
    const float* aggrow = g_agg + (size_t)amc * DD;
    const float* zrow = zsrc + (size_t)amc * DD;
    // B loader: thread -> (k-pair p = tid>>4, n offset (tid&15)*16)
    int bp = tid >> 4;
    int bnb = (tid & 15) * 16;

    float fA[16], fB0[16], fB1[16];
    auto load_regs = [&](int kc) {
        const float* ap = ((kc < 16) ? (aggrow + kc * 32)
                                     : (zrow + (kc - 16) * 32)) + ako;
        float4 q0 = ((const float4*)ap)[0], q1 = ((const float4*)ap)[1],
               q2 = ((const float4*)ap)[2], q3 = ((const float4*)ap)[3];
        fA[0]=q0.x; fA[1]=q0.y; fA[2]=q0.z; fA[3]=q0.w;
        fA[4]=q1.x; fA[5]=q1.y; fA[6]=q1.z; fA[7]=q1.w;
        fA[8]=q2.x; fA[9]=q2.y; fA[10]=q2.z; fA[11]=q2.w;
        fA[12]=q3.x; fA[13]=q3.y; fA[14]=q3.z; fA[15]=q3.w;
        int kg = kc * 32 + 2 * bp;
        const float* w0 = ((kg < DD) ? (Wl + (size_t)kg * DD)
                                     : (Wr + (size_t)(kg - DD) * DD)) + n0 + bnb;
        const float* w1 = w0 + DD;
        float4 u0 = ((const float4*)w0)[0], u1 = ((const float4*)w0)[1],
               u2 = ((const float4*)w0)[2], u3 = ((const float4*)w0)[3];
        float4 v0 = ((const float4*)w1)[0], v1 = ((const float4*)w1)[1],
               v2 = ((const float4*)w1)[2], v3 = ((const float4*)w1)[3];
        fB0[0]=u0.x; fB0[1]=u0.y; fB0[2]=u0.z; fB0[3]=u0.w;
        fB0[4]=u1.x; fB0[5]=u1.y; fB0[6]=u1.z; fB0[7]=u1.w;
        fB0[8]=u2.x; fB0[9]=u2.y; fB0[10]=u2.z; fB0[11]=u2.w;
        fB0[12]=u3.x; fB0[13]=u3.y; fB0[14]=u3.z; fB0[15]=u3.w;
        fB1[0]=v0.x; fB1[1]=v0.y; fB1[2]=v0.z; fB1[3]=v0.w;
        fB1[4]=v1.x; fB1[5]=v1.y; fB1[6]=v1.z; fB1[7]=v1.w;
        fB1[8]=v2.x; fB1[9]=v2.y; fB1[10]=v2.z; fB1[11]=v2.w;
        fB1[12]=v3.x; fB1[13]=v3.y; fB1[14]=v3.z; fB1[15]=v3.w;
    };

    load_regs(0);

    for (int kc = 0; kc < NCHK; kc++) {
        __syncthreads();   // smem consumers of previous chunk done
        // ---- store A split
        {
            int pbase = (tid & 1) * 8;
#pragma unroll
            for (int e = 0; e < 8; e++) {
                unsigned hw, lw;
                split_pack(fA[2 * e], fA[2 * e + 1], hw, lw);
                sw[AHI_W + (pbase + e) * 136 + acol] = hw;
                sw[ALO_W + (pbase + e) * 136 + acol] = lw;
            }
        }
        // ---- store B split
        {
            unsigned hib[16], lob[16];
#pragma unroll
            for (int e = 0; e < 16; e++)
                split_pack(fB0[e], fB1[e], hib[e], lob[e]);
            int wbase = bp * 264 + bnb;
#pragma unroll
            for (int q = 0; q < 4; q++) {
                *(uint4*)&sw[BHI_W + wbase + 4 * q] =
                    make_uint4(hib[4 * q], hib[4 * q + 1], hib[4 * q + 2], hib[4 * q + 3]);
                *(uint4*)&sw[BLO_W + wbase + 4 * q] =
                    make_uint4(lob[4 * q], lob[4 * q + 1], lob[4 * q + 2], lob[4 * q + 3]);
            }
        }
        __syncthreads();
        if (kc + 1 < NCHK) load_regs(kc + 1);   // prefetch overlaps mma below
        // ---- compute: 2 x k16, 3 products each
#pragma unroll
        for (int ks = 0; ks < 2; ks++) {
            int ab = (8 * ks + c) * 136 + wm * 64 + g;
            int bb = (8 * ks + c) * 264 + wn * 64 + g;
            uint32_t af[4][4], bf2[4][4];
            // P1: Ahi x Bhi
#pragma unroll
            for (int i = 0; i < 4; i++) {
                int x = AHI_W + ab + i * 16;
                af[i][0] = sw[x]; af[i][1] = sw[x + 8];
                af[i][2] = sw[x + 544]; af[i][3] = sw[x + 552];
            }
#pragma unroll
            for (int j = 0; j < 4; j++) {
                int x = BHI_W + bb + j * 16;
                bf2[j][0] = sw[x]; bf2[j][1] = sw[x + 1056];
                bf2[j][2] = sw[x + 8]; bf2[j][3] = sw[x + 1064];
            }
#pragma unroll
            for (int i = 0; i < 4; i++)
#pragma unroll
                for (int j = 0; j < 4; j++) {
                    MMA16816(acc[i][2 * j], af[i], bf2[j][0], bf2[j][1]);
                    MMA16816(acc[i][2 * j + 1], af[i], bf2[j][2], bf2[j][3]);
                }
            // P2: Ahi x Blo
#pragma unroll
            for (int j = 0; j < 4; j++) {
                int x = BLO_W + bb + j * 16;
                bf2[j][0] = sw[x]; bf2[j][1] = sw[x + 1056];
                bf2[j][2] = sw[x + 8]; bf2[j][3] = sw[x + 1064];
            }
#pragma unroll
            for (int i = 0; i < 4; i++)
#pragma unroll
                for (int j = 0; j < 4; j++) {
                    MMA16816(acc[i][2 * j], af[i], bf2[j][0], bf2[j][1]);
                    MMA16816(acc[i][2 * j + 1], af[i], bf2[j][2], bf2[j][3]);
                }
            // P3: Alo x Bhi
#pragma unroll
            for (int i = 0; i < 4; i++) {
                int x = ALO_W + ab + i * 16;
                af[i][0] = sw[x]; af[i][1] = sw[x + 8];
                af[i][2] = sw[x + 544]; af[i][3] = sw[x + 552];
            }
#pragma unroll
            for (int j = 0; j < 4; j++) {
                int x = BHI_W + bb + j * 16;
                bf2[j][0] = sw[x]; bf2[j][1] = sw[x + 1056];
                bf2[j][2] = sw[x + 8]; bf2[j][3] = sw[x + 1064];
            }
#pragma unroll
            for (int i = 0; i < 4; i++)
#pragma unroll
                for (int j = 0; j < 4; j++) {
                    MMA16816(acc[i][2 * j], af[i], bf2[j][0], bf2[j][1]);
                    MMA16816(acc[i][2 * j + 1], af[i], bf2[j][2], bf2[j][3]);
                }
        }
    }

    // ---- epilogue: bias + relu, fp32 store
    int cc = c << 1;
    float bj0[8], bj1[8];
#pragma unroll
    for (int j = 0; j < 8; j++) {
        int col = n0 + wn * 64 + j * 8 + cc;
        bj0[j] = __ldg(bias + col);
        bj1[j] = __ldg(bias + col + 1);
    }
#pragma unroll
    for (int i = 0; i < 4; i++) {
        int r0 = m0 + wm * 64 + i * 16 + g;
#pragma unroll
        for (int j = 0; j < 8; j++) {
            int col = n0 + wn * 64 + j * 8 + cc;
            float v00 = fmaxf(acc[i][j][0] + bj0[j], 0.0f);
            float v01 = fmaxf(acc[i][j][1] + bj1[j], 0.0f);
            float v10 = fmaxf(acc[i][j][2] + bj0[j], 0.0f);
            float v11 = fmaxf(acc[i][j][3] + bj1[j], 0.0f);
            if (r0 < NN)
                *(float2*)(zout + (size_t)r0 * DD + col) = make_float2(v00, v01);
            if (r0 + 8 < NN)
                *(float2*)(zout + (size_t)(r0 + 8) * DD + col) = make_float2(v10, v11);
        }
    }
}

// ---------------- launch ----------------
extern "C" void kernel_launch(void* const* d_in, const int* in_sizes, int n_in,
                              void* d_out, int out_size) {
    (void)in_sizes; (void)n_in; (void)out_size;
    const float* x  = (const float*)d_in[0];
    const void*  ei = d_in[1];
    const float* ew = (const float*)d_in[2];
    const float* Wl = (const float*)d_in[3];
    const float* Wr = (const float*)d_in[4];
    const float* b  = (const float*)d_in[5];
    float* out = (float*)d_out;

    cudaFuncSetAttribute(gemm_kernel, cudaFuncAttributeMaxDynamicSharedMemorySize, SMEM_BYTES);

    zero_small_kernel<<<(NN + 255) / 256, 256>>>();
    detect_kernel<<<1, 256>>>((const unsigned int*)ei);
    convert_kernel<<<(NE + 255) / 256, 256>>>(ei);
    degi_kernel<<<(NE + 255) / 256, 256>>>();
    scan_kernel<<<1, 1024>>>();
    fill_csr_kernel<<<(NE + 255) / 256, 256>>>(ew);

    dim3 ggrid(2, (NN + BM - 1) / BM);   // n-blocks x m-tiles

    // layer 0: x -> g_z1 ; layer 1: g_z1 -> g_z2 ; layer 2: g_z2 -> out
    for (int l = 0; l < LL; l++) {
        int insel  = (l == 0) ? 0 : l;        // 0:x 1:g_z1 2:g_z2
        int outsel = (l == LL - 1) ? 2 : l;   // 0:g_z1 1:g_z2 2:external
        gather_kernel<<<NN, 128>>>(x, insel);
        gemm_kernel<<<ggrid, 256, SMEM_BYTES>>>(x, insel,
                                                Wl + (size_t)l * DD * DD,
                                                Wr + (size_t)l * DD * DD,
                                                b + (size_t)l * DD,
                                                out, outsel);
    }
}

// round 8
// speedup vs baseline: 2.8569x; 1.3132x over previous
#include <cuda_runtime.h>
#include <cuda_fp16.h>
#include <cstdint>

#define NN 50000
#define NE 400000
#define DD 512
#define LL 3
#define BM 128
#define BN 256
#define NCHK 32            /* k chunks of 32 over K=1024 ([agg | z]) */

/* smem u32 word offsets: pair-packed tiles, padded strides (136/264) */
#define AHI_W 0
#define BHI_W 2176          /* 16*136 */
#define BLO_W 6400          /* 2176 + 16*264 */
#define SMEM_WORDS 10624
#define SMEM_BYTES (SMEM_WORDS * 4)

// ---------------- device scratch (no allocs allowed) ----------------
__device__ float g_agg[(size_t)NN * DD];
__device__ float g_z1[(size_t)NN * DD];
__device__ float g_z2[(size_t)NN * DD];
__device__ int   g_degi[NN];
__device__ int   g_off[NN + 1];
__device__ int   g_cur[NN];
__device__ int   g_csr_src[NE];
__device__ float g_csr_w[NE];
__device__ int   g_src[NE];
__device__ int   g_dst[NE];
__device__ int   g_is32;

// ---------------- helpers ----------------
__device__ __forceinline__ unsigned pack_h2(float v0, float v1) {
    __half2 h = __floats2half2_rn(v0, v1);
    return *reinterpret_cast<unsigned*>(&h);
}
// fp16 2-term split of a pair: hw = fp16(v), lw = fp16(v - fp16(v))
__device__ __forceinline__ void split_pack_f16(float v0, float v1, unsigned& hw, unsigned& lw) {
    __half h0 = __float2half_rn(v0), h1 = __float2half_rn(v1);
    float l0 = v0 - __half2float(h0), l1 = v1 - __half2float(h1);
    __half2 hh = __halves2half2(h0, h1);
    hw = *reinterpret_cast<unsigned*>(&hh);
    lw = pack_h2(l0, l1);
}

#define MMA16816(d, a, b0, b1)                                                    \
    asm volatile("mma.sync.aligned.m16n8k16.row.col.f32.f16.f16.f32 "             \
                 "{%0,%1,%2,%3}, {%4,%5,%6,%7}, {%8,%9}, {%0,%1,%2,%3};"          \
                 : "+f"((d)[0]), "+f"((d)[1]), "+f"((d)[2]), "+f"((d)[3])         \
                 : "r"((a)[0]), "r"((a)[1]), "r"((a)[2]), "r"((a)[3]),            \
                   "r"(b0), "r"(b1))

// ---------------- prep kernels ----------------
__global__ void zero_small_kernel() {
    int i = blockIdx.x * blockDim.x + threadIdx.x;
    if (i < NN) g_degi[i] = 0;
    if (i == 0) g_is32 = 0;
}

__global__ void detect_kernel(const unsigned int* __restrict__ raw) {
    unsigned acc = 0;
    for (int j = threadIdx.x; j < 4096; j += blockDim.x) acc |= raw[2 * j + 1];
    if (acc) atomicOr(&g_is32, 1);
}

__global__ void convert_kernel(const void* __restrict__ raw) {
    int e = blockIdx.x * blockDim.x + threadIdx.x;
    if (e >= NE) return;
    int s, d;
    if (g_is32) {
        const int* p = (const int*)raw;
        s = p[e]; d = p[NE + e];
    } else {
        const long long* p = (const long long*)raw;
        s = (int)p[e]; d = (int)p[NE + e];
    }
    g_src[e] = s; g_dst[e] = d;
}

__global__ void degi_kernel() {
    int e = blockIdx.x * blockDim.x + threadIdx.x;
    if (e >= NE) return;
    atomicAdd(&g_degi[g_dst[e]], 1);
}

// single-block shuffle-based exclusive scan: g_degi -> g_off, init g_cur
__global__ void scan_kernel() {
    __shared__ int wsum[32];
    __shared__ int carry;
    int t = threadIdx.x, lane = t & 31, wid = t >> 5;
    if (t == 0) { carry = 0; g_off[0] = 0; }
    __syncthreads();
    for (int base = 0; base < NN; base += 1024) {
        int i = base + t;
        int v = (i < NN) ? g_degi[i] : 0;
        int x = v;
#pragma unroll
        for (int s = 1; s < 32; s <<= 1) {
            int y = __shfl_up_sync(0xFFFFFFFF, x, s);
            if (lane >= s) x += y;
        }
        if (lane == 31) wsum[wid] = x;
        __syncthreads();
        if (wid == 0) {
            int y = wsum[lane];
#pragma unroll
            for (int s = 1; s < 32; s <<= 1) {
                int z = __shfl_up_sync(0xFFFFFFFF, y, s);
                if (lane >= s) y += z;
            }
            wsum[lane] = y;
        }
        __syncthreads();
        int add = carry + ((wid > 0) ? wsum[wid - 1] : 0);
        int incl = x + add;
        if (i < NN) {
            g_off[i + 1] = incl;
            g_cur[i] = incl - v;
        }
        __syncthreads();
        if (t == 0) carry += wsum[31];
        __syncthreads();
    }
}

__global__ void fill_csr_kernel(const float* __restrict__ ew) {
    int e = blockIdx.x * blockDim.x + threadIdx.x;
    if (e >= NE) return;
    int d = g_dst[e];
    int pos = atomicAdd(&g_cur[d], 1);
    g_csr_src[pos] = g_src[e];
    g_csr_w[pos] = ew[e];
}

// ---------------- CSR gather: agg[d] = invdeg * sum_e w_e * z[src_e] --------
__global__ void __launch_bounds__(128) gather_kernel(
    const float* __restrict__ xext, int insel) {
    const float* zin = (insel == 0) ? xext : (insel == 1 ? g_z1 : g_z2);
    int d = blockIdx.x;
    int beg = g_off[d], end = g_off[d + 1];
    float4 acc0 = make_float4(0.f, 0.f, 0.f, 0.f);
    float4 acc1 = make_float4(0.f, 0.f, 0.f, 0.f);
    int i = beg;
    for (; i + 1 < end; i += 2) {
        int s0 = __ldg(&g_csr_src[i]);
        int s1 = __ldg(&g_csr_src[i + 1]);
        float w0 = __ldg(&g_csr_w[i]);
        float w1 = __ldg(&g_csr_w[i + 1]);
        float4 v0 = ((const float4*)(zin + (size_t)s0 * DD))[threadIdx.x];
        float4 v1 = ((const float4*)(zin + (size_t)s1 * DD))[threadIdx.x];
        acc0.x += w0 * v0.x; acc0.y += w0 * v0.y;
        acc0.z += w0 * v0.z; acc0.w += w0 * v0.w;
        acc1.x += w1 * v1.x; acc1.y += w1 * v1.y;
        acc1.z += w1 * v1.z; acc1.w += w1 * v1.w;
    }
    if (i < end) {
        int s0 = __ldg(&g_csr_src[i]);
        float w0 = __ldg(&g_csr_w[i]);
        float4 v0 = ((const float4*)(zin + (size_t)s0 * DD))[threadIdx.x];
        acc0.x += w0 * v0.x; acc0.y += w0 * v0.y;
        acc0.z += w0 * v0.z; acc0.w += w0 * v0.w;
    }
    float inv = (end > beg) ? 1.0f / (float)(end - beg) : 0.0f;
    acc0.x = (acc0.x + acc1.x) * inv;
    acc0.y = (acc0.y + acc1.y) * inv;
    acc0.z = (acc0.z + acc1.z) * inv;
    acc0.w = (acc0.w + acc1.w) * inv;
    ((float4*)(g_agg + (size_t)d * DD))[threadIdx.x] = acc0;
}

// ---------------- GEMM: inline fp16 split, 2 products (AhiBhi + AhiBlo) -----
__global__ void __launch_bounds__(256, 1) gemm_kernel(
    const float* __restrict__ xext, int insel,
    const float* __restrict__ Wl, const float* __restrict__ Wr,
    const float* __restrict__ bias,
    float* __restrict__ outext, int outsel) {
    const float* zsrc = (insel == 0) ? xext : (insel == 1 ? g_z1 : g_z2);
    float* zout = (outsel == 0) ? g_z1 : (outsel == 1 ? g_z2 : outext);

    extern __shared__ uint32_t sw[];
    int tid = threadIdx.x, lane = tid & 31, warp = tid >> 5;
    int wm = warp >> 2, wn = warp & 3;
    int m0 = blockIdx.y * BM, n0 = blockIdx.x * BN;
    int g = lane >> 2, c = lane & 3;

    float acc[4][8][4];
#pragma unroll
    for (int i = 0; i < 4; i++)
#pragma unroll
        for (int j = 0; j < 8; j++)
#pragma unroll
            for (int q = 0; q < 4; q++) acc[i][j][q] = 0.0f;

    // A loader: thread -> (row m = tid>>1, k-half (tid&1)*16)
    int am = m0 + (tid >> 1);
    int amc = (am < NN) ? am : (NN - 1);
    int ako = (tid & 1) * 16;
    int acol = tid >> 1;
    const float* aggrow = g_agg + (size_t)amc * DD;
    const float* zrow = zsrc + (size_t)amc * DD;
    // B loader: thread -> (k-pair p = tid>>4, n offset (tid&15)*16)
    int bp = tid >> 4;
    int bnb = (tid & 15) * 16;

    float fA[16], fB0[16], fB1[16];
    auto load_regs = [&](int kc) {
        const float* ap = ((kc < 16) ? (aggrow + kc * 32)
                                     : (zrow + (kc - 16) * 32)) + ako;
        float4 q0 = ((const float4*)ap)[0], q1 = ((const float4*)ap)[1],
               q2 = ((const float4*)ap)[2], q3 = ((const float4*)ap)[3];
        fA[0]=q0.x; fA[1]=q0.y; fA[2]=q0.z; fA[3]=q0.w;
        fA[4]=q1.x; fA[5]=q1.y; fA[6]=q1.z; fA[7]=q1.w;
        fA[8]=q2.x; fA[9]=q2.y; fA[10]=q2.z; fA[11]=q2.w;
        fA[12]=q3.x; fA[13]=q3.y; fA[14]=q3.z; fA[15]=q3.w;
        int kg = kc * 32 + 2 * bp;
        const float* w0 = ((kg < DD) ? (Wl + (size_t)kg * DD)
                                     : (Wr + (size_t)(kg - DD) * DD)) + n0 + bnb;
        const float* w1 = w0 + DD;
        float4 u0 = ((const float4*)w0)[0], u1 = ((const float4*)w0)[1],
               u2 = ((const float4*)w0)[2], u3 = ((const float4*)w0)[3];
        float4 v0 = ((const float4*)w1)[0], v1 = ((const float4*)w1)[1],
               v2 = ((const float4*)w1)[2], v3 = ((const float4*)w1)[3];
        fB0[0]=u0.x; fB0[1]=u0.y; fB0[2]=u0.z; fB0[3]=u0.w;
        fB0[4]=u1.x; fB0[5]=u1.y; fB0[6]=u1.z; fB0[7]=u1.w;
        fB0[8]=u2.x; fB0[9]=u2.y; fB0[10]=u2.z; fB0[11]=u2.w;
        fB0[12]=u3.x; fB0[13]=u3.y; fB0[14]=u3.z; fB0[15]=u3.w;
        fB1[0]=v0.x; fB1[1]=v0.y; fB1[2]=v0.z; fB1[3]=v0.w;
        fB1[4]=v1.x; fB1[5]=v1.y; fB1[6]=v1.z; fB1[7]=v1.w;
        fB1[8]=v2.x; fB1[9]=v2.y; fB1[10]=v2.z; fB1[11]=v2.w;
        fB1[12]=v3.x; fB1[13]=v3.y; fB1[14]=v3.z; fB1[15]=v3.w;
    };

    load_regs(0);

    for (int kc = 0; kc < NCHK; kc++) {
        __syncthreads();
        // ---- store A (hi only): pack fp16 pairs
        {
            int pbase = (tid & 1) * 8;
#pragma unroll
            for (int e = 0; e < 8; e++)
                sw[AHI_W + (pbase + e) * 136 + acol] = pack_h2(fA[2 * e], fA[2 * e + 1]);
        }
        // ---- store B hi/lo split
        {
            unsigned hib[16], lob[16];
#pragma unroll
            for (int e = 0; e < 16; e++)
                split_pack_f16(fB0[e], fB1[e], hib[e], lob[e]);  // pair (k=2p, 2p+1)
            int wbase = bp * 264 + bnb;
#pragma unroll
            for (int q = 0; q < 4; q++) {
                *(uint4*)&sw[BHI_W + wbase + 4 * q] =
                    make_uint4(hib[4 * q], hib[4 * q + 1], hib[4 * q + 2], hib[4 * q + 3]);
                *(uint4*)&sw[BLO_W + wbase + 4 * q] =
                    make_uint4(lob[4 * q], lob[4 * q + 1], lob[4 * q + 2], lob[4 * q + 3]);
            }
        }
        __syncthreads();
        if (kc + 1 < NCHK) load_regs(kc + 1);   // prefetch overlaps mma below
        // ---- compute: 2 x k16, 2 products each
#pragma unroll
        for (int ks = 0; ks < 2; ks++) {
            int ab = (8 * ks + c) * 136 + wm * 64 + g;
            int bb = (8 * ks + c) * 264 + wn * 64 + g;
            uint32_t af[4][4], bf2[4][4];
#pragma unroll
            for (int i = 0; i < 4; i++) {
                int x = AHI_W + ab + i * 16;
                af[i][0] = sw[x]; af[i][1] = sw[x + 8];
                af[i][2] = sw[x + 544]; af[i][3] = sw[x + 552];
            }
            // P1: Ahi x Bhi
#pragma unroll
            for (int j = 0; j < 4; j++) {
                int x = BHI_W + bb + j * 16;
                bf2[j][0] = sw[x]; bf2[j][1] = sw[x + 1056];
                bf2[j][2] = sw[x + 8]; bf2[j][3] = sw[x + 1064];
            }
#pragma unroll
            for (int i = 0; i < 4; i++)
#pragma unroll
                for (int j = 0; j < 4; j++) {
                    MMA16816(acc[i][2 * j], af[i], bf2[j][0], bf2[j][1]);
                    MMA16816(acc[i][2 * j + 1], af[i], bf2[j][2], bf2[j][3]);
                }
            // P2: Ahi x Blo
#pragma unroll
            for (int j = 0; j < 4; j++) {
                int x = BLO_W + bb + j * 16;
                bf2[j][0] = sw[x]; bf2[j][1] = sw[x + 1056];
                bf2[j][2] = sw[x + 8]; bf2[j][3] = sw[x + 1064];
            }
#pragma unroll
            for (int i = 0; i < 4; i++)
#pragma unroll
                for (int j = 0; j < 4; j++) {
                    MMA16816(acc[i][2 * j], af[i], bf2[j][0], bf2[j][1]);
                    MMA16816(acc[i][2 * j + 1], af[i], bf2[j][2], bf2[j][3]);
                }
        }
    }

    // ---- epilogue: bias + relu, fp32 store
    int cc = c << 1;
    float bj0[8], bj1[8];
#pragma unroll
    for (int j = 0; j < 8; j++) {
        int col = n0 + wn * 64 + j * 8 + cc;
        bj0[j] = __ldg(bias + col);
        bj1[j] = __ldg(bias + col + 1);
    }
#pragma unroll
    for (int i = 0; i < 4; i++) {
        int r0 = m0 + wm * 64 + i * 16 + g;
#pragma unroll
        for (int j = 0; j < 8; j++) {
            int col = n0 + wn * 64 + j * 8 + cc;
            float v00 = fmaxf(acc[i][j][0] + bj0[j], 0.0f);
            float v01 = fmaxf(acc[i][j][1] + bj1[j], 0.0f);
            float v10 = fmaxf(acc[i][j][2] + bj0[j], 0.0f);
            float v11 = fmaxf(acc[i][j][3] + bj1[j], 0.0f);
            if (r0 < NN)
                *(float2*)(zout + (size_t)r0 * DD + col) = make_float2(v00, v01);
            if (r0 + 8 < NN)
                *(float2*)(zout + (size_t)(r0 + 8) * DD + col) = make_float2(v10, v11);
        }
    }
}

// ---------------- launch ----------------
extern "C" void kernel_launch(void* const* d_in, const int* in_sizes, int n_in,
                              void* d_out, int out_size) {
    (void)in_sizes; (void)n_in; (void)out_size;
    const float* x  = (const float*)d_in[0];
    const void*  ei = d_in[1];
    const float* ew = (const float*)d_in[2];
    const float* Wl = (const float*)d_in[3];
    const float* Wr = (const float*)d_in[4];
    const float* b  = (const float*)d_in[5];
    float* out = (float*)d_out;

    cudaFuncSetAttribute(gemm_kernel, cudaFuncAttributeMaxDynamicSharedMemorySize, SMEM_BYTES);

    zero_small_kernel<<<(NN + 255) / 256, 256>>>();
    detect_kernel<<<1, 256>>>((const unsigned int*)ei);
    convert_kernel<<<(NE + 255) / 256, 256>>>(ei);
    degi_kernel<<<(NE + 255) / 256, 256>>>();
    scan_kernel<<<1, 1024>>>();
    fill_csr_kernel<<<(NE + 255) / 256, 256>>>(ew);

    dim3 ggrid(2, (NN + BM - 1) / BM);   // n-blocks x m-tiles

    // layer 0: x -> g_z1 ; layer 1: g_z1 -> g_z2 ; layer 2: g_z2 -> out
    for (int l = 0; l < LL; l++) {
        int insel  = (l == 0) ? 0 : l;        // 0:x 1:g_z1 2:g_z2
        int outsel = (l == LL - 1) ? 2 : l;   // 0:g_z1 1:g_z2 2:external
        gather_kernel<<<NN, 128>>>(x, insel);
        gemm_kernel<<<ggrid, 256, SMEM_BYTES>>>(x, insel,
                                                Wl + (size_t)l * DD * DD,
                                                Wr + (size_t)l * DD * DD,
                                                b + (size_t)l * DD,
                                                out, outsel);
    }
}